// round 14
// baseline (speedup 1.0000x reference)
#include <cuda_runtime.h>
#include <cuda_fp16.h>

#define L_TOTAL 32768
#define KQ      1024
#define EDIM    64
#define MT      32             // latents per CTA (2 tiles x 16)
#define KHALF   512            // codes per k-split half
#define CHK     32             // codes per staged chunk per half
#define NCHUNK  (KHALF / CHK)  // 16
#define SROW    72             // padded smem row stride (halves) -> conflict-free
#define THREADS 128
#define GUARD   4e-2f

// scratch tables (no cudaMalloc allowed)
__device__ float  g_c[KQ];             // ||e_k||^2 (fp32)
__device__ __half g_ehi[KQ * EDIM];    // fp16-rounded embeddings [k][e]

__device__ __forceinline__ void mma16816(float* d, const unsigned* a,
                                         unsigned b0, unsigned b1) {
    asm volatile(
        "mma.sync.aligned.m16n8k16.row.col.f32.f16.f16.f32 "
        "{%0,%1,%2,%3}, {%4,%5,%6,%7}, {%8,%9}, {%0,%1,%2,%3};"
        : "+f"(d[0]), "+f"(d[1]), "+f"(d[2]), "+f"(d[3])
        : "r"(a[0]), "r"(a[1]), "r"(a[2]), "r"(a[3]), "r"(b0), "r"(b1));
}

__device__ __forceinline__ void ldsm4(unsigned& r0, unsigned& r1,
                                      unsigned& r2, unsigned& r3,
                                      unsigned addr) {
    asm volatile("ldmatrix.sync.aligned.m8n8.x4.shared.b16 {%0,%1,%2,%3}, [%4];"
                 : "=r"(r0), "=r"(r1), "=r"(r2), "=r"(r3) : "r"(addr));
}

__device__ __forceinline__ unsigned packhi(float a, float b) {
    __half2 H = __halves2half2(__float2half_rn(a), __float2half_rn(b));
    return *reinterpret_cast<unsigned*>(&H);
}

__device__ __forceinline__ void cp16(void* dst_smem, const void* src) {
    unsigned d = (unsigned)__cvta_generic_to_shared(dst_smem);
    asm volatile("cp.async.cg.shared.global [%0], [%1], 16;"
                 :: "r"(d), "l"(src) : "memory");
}

// Parallel prep: 8 threads per code row. ||e||^2 via 8-lane shfl tree.
__global__ void vq_prep_kernel(const float* __restrict__ emb) {
    int t   = blockIdx.x * blockDim.x + threadIdx.x;  // 0..8191
    int k   = t >> 3;
    int seg = t & 7;
    const float4* p = reinterpret_cast<const float4*>(emb + k * EDIM + seg * 8);
    float4 v0 = p[0], v1 = p[1];
    float s = v0.x * v0.x + v0.y * v0.y + v0.z * v0.z + v0.w * v0.w
            + v1.x * v1.x + v1.y * v1.y + v1.z * v1.z + v1.w * v1.w;
    uint4 H;
    H.x = packhi(v0.x, v0.y);
    H.y = packhi(v0.z, v0.w);
    H.z = packhi(v1.x, v1.y);
    H.w = packhi(v1.z, v1.w);
    *reinterpret_cast<uint4*>(&g_ehi[k * EDIM + seg * 8]) = H;
    s += __shfl_xor_sync(0xffffffffu, s, 1);
    s += __shfl_xor_sync(0xffffffffu, s, 2);
    s += __shfl_xor_sync(0xffffffffu, s, 4);
    if (seg == 0) g_c[k] = s;
}

struct Top3 { float b1, b2, b3; int i1, i2, i3; };

__device__ __forceinline__ void upd3(Top3& t, float s, int c) {
    if (s < t.b1) {
        t.b3 = t.b2; t.i3 = t.i2;
        t.b2 = t.b1; t.i2 = t.i1;
        t.b1 = s;    t.i1 = c;
    } else if (s < t.b2) {
        t.b3 = t.b2; t.i3 = t.i2;
        t.b2 = s;    t.i2 = c;
    } else if (s < t.b3) {
        t.b3 = s;    t.i3 = c;
    }
}

// Insert a candidate from another lane/half (index tie-break, first-min).
__device__ __forceinline__ void ins3(Top3& t, float ob, int oi) {
    if (ob < t.b1 || (ob == t.b1 && oi < t.i1)) {
        t.b3 = t.b2; t.i3 = t.i2;
        t.b2 = t.b1; t.i2 = t.i1;
        t.b1 = ob;   t.i1 = oi;
    } else if (ob < t.b2 || (ob == t.b2 && oi < t.i2)) {
        t.b3 = t.b2; t.i3 = t.i2;
        t.b2 = ob;   t.i2 = oi;
    } else if (ob < t.b3 || (ob == t.b3 && oi < t.i3)) {
        t.b3 = ob;   t.i3 = oi;
    }
}

__global__ void __launch_bounds__(THREADS, 7)
vq_mma_kernel(const float* __restrict__ x,
              const float* __restrict__ emb,
              float* __restrict__ out) {
    // [buf][half] double-buffered hi-only code chunks
    __shared__ __align__(16) __half sB[2][2][CHK * SROW];
    __shared__ float cs[KQ];
    __shared__ float mb1[MT], mb2[MT], mb3[MT];
    __shared__ int   mi1[MT], mi2[MT], mi3[MT];
    __shared__ int   sidx[MT];

    const int tid   = threadIdx.x;
    const int warp  = tid >> 5;
    const int lane  = tid & 31;
    const int g     = lane >> 2;       // row within m16 tile
    const int T     = lane & 3;        // thread in quad
    const int tile  = warp & 1;        // which 16-latent tile
    const int khalf = warp >> 1;       // which 512-code half
    const int lbase = blockIdx.x * MT;

    // stage ||e||^2
    #pragma unroll
    for (int i = 0; i < KQ / THREADS; i++)
        cs[tid + i * THREADS] = g_c[tid + i * THREADS];

    // Stage chunk ch (both halves, hi only): 512 16B moves -> 4 per thread.
    auto stage = [&](int ch, int buf) {
        #pragma unroll
        for (int i = 0; i < 4; i++) {
            int u    = tid + i * THREADS;      // 0..511
            int seg  = u & 7;
            int row  = (u >> 3) & 31;
            int half = u >> 8;
            cp16(&sB[buf][half][row * SROW + seg * 8],
                 &g_ehi[(size_t)(half * KHALF + ch * CHK + row) * EDIM + seg * 8]);
        }
        asm volatile("cp.async.commit_group;" ::: "memory");
    };

    stage(0, 0);

    // ldmatrix per-lane base offsets (verified mapping, rel_err 0.0):
    const unsigned lane_off =
        (unsigned)(((lane & 7) + ((lane >> 4) << 3)) * (SROW * 2)
                   + ((lane >> 3) & 1) * 16);
    const unsigned sm_hi0 =
        (unsigned)__cvta_generic_to_shared(&sB[0][khalf][0]) + lane_off;
    const unsigned BUFSTRIDE = 2u * CHK * SROW * 2u;   // bytes per buf

    // A fragments: rows r0 = tile*16+g, r1 = r0+8 of (-2x), fp16-hi only.
    unsigned ahi[4][4];
    {
        const float* xr0 = x + (size_t)(lbase + tile * 16 + g) * EDIM;
        const float* xr1 = xr0 + 8 * EDIM;
        #pragma unroll
        for (int ks = 0; ks < 4; ks++) {
            int c0 = 16 * ks + 2 * T;
            float2 v;
            v = *reinterpret_cast<const float2*>(xr0 + c0);
            ahi[ks][0] = packhi(-2.f * v.x, -2.f * v.y);
            v = *reinterpret_cast<const float2*>(xr1 + c0);
            ahi[ks][1] = packhi(-2.f * v.x, -2.f * v.y);
            v = *reinterpret_cast<const float2*>(xr0 + c0 + 8);
            ahi[ks][2] = packhi(-2.f * v.x, -2.f * v.y);
            v = *reinterpret_cast<const float2*>(xr1 + c0 + 8);
            ahi[ks][3] = packhi(-2.f * v.x, -2.f * v.y);
        }
    }

    Top3 tp[2];
    tp[0].b1 = tp[0].b2 = tp[0].b3 = 3.4e38f;
    tp[0].i1 = tp[0].i2 = tp[0].i3 = 0;
    tp[1] = tp[0];

    asm volatile("cp.async.wait_group 0;" ::: "memory");
    __syncthreads();   // covers cs staging + chunk 0

    int buf = 0;
    #pragma unroll 1
    for (int ch = 0; ch < NCHUNK; ch++) {
        if (ch + 1 < NCHUNK) stage(ch + 1, buf ^ 1);   // overlap next stage

        const unsigned base0 = sm_hi0 + (unsigned)buf * BUFSTRIDE;
        const int c0 = khalf * KHALF + ch * CHK;

        // CHK=32 -> two n16-tiles per chunk; single hi-pass MMA.
        #pragma unroll
        for (int nt = 0; nt < 2; nt++) {
            const unsigned base = base0 + (unsigned)(nt * 16 * SROW * 2);
            unsigned h0[4], h1[4], h2[4], h3[4];
            ldsm4(h0[0], h0[1], h0[2], h0[3], base);
            ldsm4(h1[0], h1[1], h1[2], h1[3], base + 32);
            ldsm4(h2[0], h2[1], h2[2], h2[3], base + 64);
            ldsm4(h3[0], h3[1], h3[2], h3[3], base + 96);
            float d[2][4] = {{0,0,0,0},{0,0,0,0}};
            #pragma unroll
            for (int j = 0; j < 2; j++) {
                mma16816(d[j], ahi[0], h0[2*j], h0[2*j+1]);
                mma16816(d[j], ahi[1], h1[2*j], h1[2*j+1]);
                mma16816(d[j], ahi[2], h2[2*j], h2[2*j+1]);
                mma16816(d[j], ahi[3], h3[2*j], h3[2*j+1]);
            }
            #pragma unroll
            for (int j = 0; j < 2; j++) {
                int col = c0 + nt * 16 + 8 * j + 2 * T;
                upd3(tp[0], cs[col]     + d[j][0], col);
                upd3(tp[0], cs[col + 1] + d[j][1], col + 1);
                upd3(tp[1], cs[col]     + d[j][2], col);
                upd3(tp[1], cs[col + 1] + d[j][3], col + 1);
            }
        }

        asm volatile("cp.async.wait_group 0;" ::: "memory");
        __syncthreads();
        buf ^= 1;
    }

    // Reduce across the 4 lanes of each quad (xor 1, 2 stay in-quad).
    // Lanes hold disjoint code sets; sorted insertion keeps exact top-3.
    #pragma unroll
    for (int s = 0; s < 2; s++) {
        #pragma unroll
        for (int m = 1; m < 4; m <<= 1) {
            float ob1 = __shfl_xor_sync(0xffffffffu, tp[s].b1, m);
            float ob2 = __shfl_xor_sync(0xffffffffu, tp[s].b2, m);
            float ob3 = __shfl_xor_sync(0xffffffffu, tp[s].b3, m);
            int   oi1 = __shfl_xor_sync(0xffffffffu, tp[s].i1, m);
            int   oi2 = __shfl_xor_sync(0xffffffffu, tp[s].i2, m);
            int   oi3 = __shfl_xor_sync(0xffffffffu, tp[s].i3, m);
            ins3(tp[s], ob1, oi1);
            ins3(tp[s], ob2, oi2);
            ins3(tp[s], ob3, oi3);
        }
    }

    // k-half merge: khalf1 publishes top-3, khalf0 inserts.
    if (khalf == 1 && T == 0) {
        #pragma unroll
        for (int s = 0; s < 2; s++) {
            int lr = tile * 16 + g + 8 * s;
            mb1[lr] = tp[s].b1; mi1[lr] = tp[s].i1;
            mb2[lr] = tp[s].b2; mi2[lr] = tp[s].i2;
            mb3[lr] = tp[s].b3; mi3[lr] = tp[s].i3;
        }
    }
    __syncthreads();

    if (khalf == 0 && T == 0) {
        #pragma unroll
        for (int s = 0; s < 2; s++) {
            int lr = tile * 16 + g + 8 * s;
            ins3(tp[s], mb1[lr], mi1[lr]);
            ins3(tp[s], mb2[lr], mi2[lr]);
            ins3(tp[s], mb3[lr], mi3[lr]);

            int win = tp[s].i1;
            // 1-pass guard: exact fp32 recheck of all close candidates.
            if (tp[s].b2 - tp[s].b1 < GUARD) {
                const float* xr  = x   + (size_t)(lbase + lr) * EDIM;
                const float* e1r = emb + (size_t)tp[s].i1 * EDIM;
                const float* e2r = emb + (size_t)tp[s].i2 * EDIM;
                float d1 = 0.f, d2 = 0.f;
                #pragma unroll 8
                for (int e = 0; e < EDIM; e++) {
                    float xv = xr[e];
                    d1 = fmaf(xv, e1r[e], d1);
                    d2 = fmaf(xv, e2r[e], d2);
                }
                float s1 = fmaf(-2.f, d1, cs[tp[s].i1]);
                float s2 = fmaf(-2.f, d2, cs[tp[s].i2]);
                float bs = s1; int bi = tp[s].i1;
                if (s2 < bs || (s2 == bs && tp[s].i2 < bi)) { bs = s2; bi = tp[s].i2; }
                if (tp[s].b3 - tp[s].b1 < GUARD) {
                    const float* e3r = emb + (size_t)tp[s].i3 * EDIM;
                    float d3 = 0.f;
                    #pragma unroll 8
                    for (int e = 0; e < EDIM; e++)
                        d3 = fmaf(xr[e], e3r[e], d3);
                    float s3 = fmaf(-2.f, d3, cs[tp[s].i3]);
                    if (s3 < bs || (s3 == bs && tp[s].i3 < bi)) { bs = s3; bi = tp[s].i3; }
                }
                win = bi;
            }
            sidx[lr] = win;
        }
    }
    __syncthreads();

    // Coalesced epilogue: out = [x | quantized | z_hat | indices], fp32.
    const size_t LE4 = (size_t)L_TOTAL * (EDIM / 4);
    const float4* x4  = reinterpret_cast<const float4*>(x);
    const float4* e4p = reinterpret_cast<const float4*>(emb);
    float4* out4 = reinterpret_cast<float4*>(out);
    #pragma unroll
    for (int i = 0; i < (MT * EDIM / 4) / THREADS; i++) {
        int idx = tid + i * THREADS;
        int l = idx >> 4, c4 = idx & 15;
        size_t goff = (size_t)(lbase + l) * 16 + c4;
        float4 xv = x4[goff];
        float4 qv = e4p[(size_t)sidx[l] * 16 + c4];
        out4[goff] = xv;
        out4[LE4 + goff] = qv;
        float4 zh;
        zh.x = (xv.x + qv.x) - xv.x;
        zh.y = (xv.y + qv.y) - xv.y;
        zh.z = (xv.z + qv.z) - xv.z;
        zh.w = (xv.w + qv.w) - xv.w;
        out4[2 * LE4 + goff] = zh;
    }
    if (tid < MT)
        out[3 * (size_t)L_TOTAL * EDIM + lbase + tid] = (float)sidx[tid];
}

extern "C" void kernel_launch(void* const* d_in, const int* in_sizes, int n_in,
                              void* d_out, int out_size) {
    const float* x   = (const float*)d_in[0];
    const float* emb = (const float*)d_in[1];
    float* out       = (float*)d_out;

    vq_prep_kernel<<<64, 128>>>(emb);
    vq_mma_kernel<<<L_TOTAL / MT, THREADS>>>(x, emb, out);
}

// round 15
// speedup vs baseline: 1.4216x; 1.4216x over previous
#include <cuda_runtime.h>
#include <cuda_fp16.h>

#define L_TOTAL 32768
#define KQ      1024
#define EDIM    64
#define MT      32             // latents per CTA (2 tiles x 16)
#define KHALF   512            // codes per k-split half
#define CHK     32             // codes per staged chunk per half
#define NCHUNK  (KHALF / CHK)  // 16
#define SROW    72             // padded smem row stride (halves) -> conflict-free
#define THREADS 128
#define GUARD   8e-2f
#define OFFS    64.0f          // positivity offset folded into MMA accum init

// scratch tables (no cudaMalloc allowed)
__device__ float  g_c[KQ];             // ||e_k||^2 (fp32)
__device__ __half g_ehi[KQ * EDIM];    // fp16-rounded embeddings [k][e]

__device__ __forceinline__ void mma16816(float* d, const unsigned* a,
                                         unsigned b0, unsigned b1) {
    asm volatile(
        "mma.sync.aligned.m16n8k16.row.col.f32.f16.f16.f32 "
        "{%0,%1,%2,%3}, {%4,%5,%6,%7}, {%8,%9}, {%0,%1,%2,%3};"
        : "+f"(d[0]), "+f"(d[1]), "+f"(d[2]), "+f"(d[3])
        : "r"(a[0]), "r"(a[1]), "r"(a[2]), "r"(a[3]), "r"(b0), "r"(b1));
}

__device__ __forceinline__ void ldsm4(unsigned& r0, unsigned& r1,
                                      unsigned& r2, unsigned& r3,
                                      unsigned addr) {
    asm volatile("ldmatrix.sync.aligned.m8n8.x4.shared.b16 {%0,%1,%2,%3}, [%4];"
                 : "=r"(r0), "=r"(r1), "=r"(r2), "=r"(r3) : "r"(addr));
}

__device__ __forceinline__ unsigned packhi(float a, float b) {
    __half2 H = __halves2half2(__float2half_rn(a), __float2half_rn(b));
    return *reinterpret_cast<unsigned*>(&H);
}

__device__ __forceinline__ void cp16(void* dst_smem, const void* src) {
    unsigned d = (unsigned)__cvta_generic_to_shared(dst_smem);
    asm volatile("cp.async.cg.shared.global [%0], [%1], 16;"
                 :: "r"(d), "l"(src) : "memory");
}

// Parallel prep: 8 threads per code row. ||e||^2 via 8-lane shfl tree.
__global__ void vq_prep_kernel(const float* __restrict__ emb) {
    int t   = blockIdx.x * blockDim.x + threadIdx.x;  // 0..8191
    int k   = t >> 3;
    int seg = t & 7;
    const float4* p = reinterpret_cast<const float4*>(emb + k * EDIM + seg * 8);
    float4 v0 = p[0], v1 = p[1];
    float s = v0.x * v0.x + v0.y * v0.y + v0.z * v0.z + v0.w * v0.w
            + v1.x * v1.x + v1.y * v1.y + v1.z * v1.z + v1.w * v1.w;
    uint4 H;
    H.x = packhi(v0.x, v0.y);
    H.y = packhi(v0.z, v0.w);
    H.z = packhi(v1.x, v1.y);
    H.w = packhi(v1.z, v1.w);
    *reinterpret_cast<uint4*>(&g_ehi[k * EDIM + seg * 8]) = H;
    s += __shfl_xor_sync(0xffffffffu, s, 1);
    s += __shfl_xor_sync(0xffffffffu, s, 2);
    s += __shfl_xor_sync(0xffffffffu, s, 4);
    if (seg == 0) g_c[k] = s;
}

// Packed top-3: scores carry their code index in the low 10 mantissa bits.
// All values positive -> float order == integer order; lower index wins ties.
struct Top3p { float m1, m2, m3; };

__device__ __forceinline__ void ins3p(Top3p& t, float s) {
    float a = fmaxf(t.m1, s);
    t.m1    = fminf(t.m1, s);
    float b = fmaxf(t.m2, a);
    t.m2    = fminf(t.m2, a);
    t.m3    = fminf(t.m3, b);
}

__device__ __forceinline__ float packidx(float s, int col) {
    return __uint_as_float((__float_as_uint(s) & ~1023u) | (unsigned)col);
}

__global__ void __launch_bounds__(THREADS, 7)
vq_mma_kernel(const float* __restrict__ x,
              const float* __restrict__ emb,
              float* __restrict__ out) {
    // [buf][half] double-buffered hi-only code chunks
    __shared__ __align__(16) __half sB[2][2][CHK * SROW];
    __shared__ float cs[KQ];
    __shared__ float mb[3][MT];
    __shared__ int   sidx[MT];

    const int tid   = threadIdx.x;
    const int warp  = tid >> 5;
    const int lane  = tid & 31;
    const int g     = lane >> 2;       // row within m16 tile
    const int T     = lane & 3;        // thread in quad
    const int tile  = warp & 1;        // which 16-latent tile
    const int khalf = warp >> 1;       // which 512-code half
    const int lbase = blockIdx.x * MT;

    // stage ||e||^2
    #pragma unroll
    for (int i = 0; i < KQ / THREADS; i++)
        cs[tid + i * THREADS] = g_c[tid + i * THREADS];

    // Stage chunk ch (both halves, hi only): 512 16B moves -> 4 per thread.
    auto stage = [&](int ch, int buf) {
        #pragma unroll
        for (int i = 0; i < 4; i++) {
            int u    = tid + i * THREADS;      // 0..511
            int seg  = u & 7;
            int row  = (u >> 3) & 31;
            int half = u >> 8;
            cp16(&sB[buf][half][row * SROW + seg * 8],
                 &g_ehi[(size_t)(half * KHALF + ch * CHK + row) * EDIM + seg * 8]);
        }
        asm volatile("cp.async.commit_group;" ::: "memory");
    };

    stage(0, 0);

    // ldmatrix per-lane base offsets (verified mapping, rel_err 0.0):
    const unsigned lane_off =
        (unsigned)(((lane & 7) + ((lane >> 4) << 3)) * (SROW * 2)
                   + ((lane >> 3) & 1) * 16);
    const unsigned sm_hi0 =
        (unsigned)__cvta_generic_to_shared(&sB[0][khalf][0]) + lane_off;
    const unsigned BUFSTRIDE = 2u * CHK * SROW * 2u;   // bytes per buf

    // A fragments: rows r0 = tile*16+g, r1 = r0+8 of (-2x), fp16-hi only.
    unsigned ahi[4][4];
    {
        const float* xr0 = x + (size_t)(lbase + tile * 16 + g) * EDIM;
        const float* xr1 = xr0 + 8 * EDIM;
        #pragma unroll
        for (int ks = 0; ks < 4; ks++) {
            int c0 = 16 * ks + 2 * T;
            float2 v;
            v = *reinterpret_cast<const float2*>(xr0 + c0);
            ahi[ks][0] = packhi(-2.f * v.x, -2.f * v.y);
            v = *reinterpret_cast<const float2*>(xr1 + c0);
            ahi[ks][1] = packhi(-2.f * v.x, -2.f * v.y);
            v = *reinterpret_cast<const float2*>(xr0 + c0 + 8);
            ahi[ks][2] = packhi(-2.f * v.x, -2.f * v.y);
            v = *reinterpret_cast<const float2*>(xr1 + c0 + 8);
            ahi[ks][3] = packhi(-2.f * v.x, -2.f * v.y);
        }
    }

    Top3p tp[2];
    tp[0].m1 = tp[0].m2 = tp[0].m3 = 3.4e38f;
    tp[1] = tp[0];

    asm volatile("cp.async.wait_group 0;" ::: "memory");
    __syncthreads();   // covers cs staging + chunk 0

    int buf = 0;
    #pragma unroll 1
    for (int ch = 0; ch < NCHUNK; ch++) {
        if (ch + 1 < NCHUNK) stage(ch + 1, buf ^ 1);   // overlap next stage

        const unsigned base0 = sm_hi0 + (unsigned)buf * BUFSTRIDE;
        const int c0 = khalf * KHALF + ch * CHK;

        // CHK=32 -> two n16-tiles per chunk; single hi-pass MMA.
        #pragma unroll
        for (int nt = 0; nt < 2; nt++) {
            const unsigned base = base0 + (unsigned)(nt * 16 * SROW * 2);
            unsigned h0[4], h1[4], h2[4], h3[4];
            ldsm4(h0[0], h0[1], h0[2], h0[3], base);
            ldsm4(h1[0], h1[1], h1[2], h1[3], base + 32);
            ldsm4(h2[0], h2[1], h2[2], h2[3], base + 64);
            ldsm4(h3[0], h3[1], h3[2], h3[3], base + 96);
            // d init = OFFS folds the positivity offset in for free.
            float d[2][4] = {{OFFS,OFFS,OFFS,OFFS},{OFFS,OFFS,OFFS,OFFS}};
            #pragma unroll
            for (int j = 0; j < 2; j++) {
                mma16816(d[j], ahi[0], h0[2*j], h0[2*j+1]);
                mma16816(d[j], ahi[1], h1[2*j], h1[2*j+1]);
                mma16816(d[j], ahi[2], h2[2*j], h2[2*j+1]);
                mma16816(d[j], ahi[3], h3[2*j], h3[2*j+1]);
            }
            #pragma unroll
            for (int j = 0; j < 2; j++) {
                int col = c0 + nt * 16 + 8 * j + 2 * T;
                ins3p(tp[0], packidx(cs[col]     + d[j][0], col));
                ins3p(tp[0], packidx(cs[col + 1] + d[j][1], col + 1));
                ins3p(tp[1], packidx(cs[col]     + d[j][2], col));
                ins3p(tp[1], packidx(cs[col + 1] + d[j][3], col + 1));
            }
        }

        asm volatile("cp.async.wait_group 0;" ::: "memory");
        __syncthreads();
        buf ^= 1;
    }

    // Reduce across the 4 lanes of each quad (xor 1, 2 stay in-quad).
    #pragma unroll
    for (int s = 0; s < 2; s++) {
        #pragma unroll
        for (int m = 1; m < 4; m <<= 1) {
            float o1 = __shfl_xor_sync(0xffffffffu, tp[s].m1, m);
            float o2 = __shfl_xor_sync(0xffffffffu, tp[s].m2, m);
            float o3 = __shfl_xor_sync(0xffffffffu, tp[s].m3, m);
            ins3p(tp[s], o1);
            ins3p(tp[s], o2);
            ins3p(tp[s], o3);
        }
    }

    // k-half merge: khalf1 publishes top-3, khalf0 inserts.
    if (khalf == 1 && T == 0) {
        #pragma unroll
        for (int s = 0; s < 2; s++) {
            int lr = tile * 16 + g + 8 * s;
            mb[0][lr] = tp[s].m1;
            mb[1][lr] = tp[s].m2;
            mb[2][lr] = tp[s].m3;
        }
    }
    __syncthreads();

    if (khalf == 0 && T == 0) {
        #pragma unroll
        for (int s = 0; s < 2; s++) {
            int lr = tile * 16 + g + 8 * s;
            ins3p(tp[s], mb[0][lr]);
            ins3p(tp[s], mb[1][lr]);
            ins3p(tp[s], mb[2][lr]);

            int i1 = (int)(__float_as_uint(tp[s].m1) & 1023u);
            int win = i1;
            // Guard: exact fp32 recheck of all close candidates.
            if (tp[s].m2 - tp[s].m1 < GUARD) {
                int i2 = (int)(__float_as_uint(tp[s].m2) & 1023u);
                const float* xr  = x   + (size_t)(lbase + lr) * EDIM;
                const float* e1r = emb + (size_t)i1 * EDIM;
                const float* e2r = emb + (size_t)i2 * EDIM;
                float d1 = 0.f, d2 = 0.f;
                #pragma unroll 8
                for (int e = 0; e < EDIM; e++) {
                    float xv = xr[e];
                    d1 = fmaf(xv, e1r[e], d1);
                    d2 = fmaf(xv, e2r[e], d2);
                }
                float s1 = fmaf(-2.f, d1, cs[i1]);
                float s2 = fmaf(-2.f, d2, cs[i2]);
                float bs = s1; int bi = i1;
                if (s2 < bs || (s2 == bs && i2 < bi)) { bs = s2; bi = i2; }
                if (tp[s].m3 - tp[s].m1 < GUARD) {
                    int i3 = (int)(__float_as_uint(tp[s].m3) & 1023u);
                    const float* e3r = emb + (size_t)i3 * EDIM;
                    float d3 = 0.f;
                    #pragma unroll 8
                    for (int e = 0; e < EDIM; e++)
                        d3 = fmaf(xr[e], e3r[e], d3);
                    float s3 = fmaf(-2.f, d3, cs[i3]);
                    if (s3 < bs || (s3 == bs && i3 < bi)) { bs = s3; bi = i3; }
                }
                win = bi;
            }
            sidx[lr] = win;
        }
    }
    __syncthreads();

    // Coalesced epilogue: out = [x | quantized | z_hat | indices], fp32.
    const size_t LE4 = (size_t)L_TOTAL * (EDIM / 4);
    const float4* x4  = reinterpret_cast<const float4*>(x);
    const float4* e4p = reinterpret_cast<const float4*>(emb);
    float4* out4 = reinterpret_cast<float4*>(out);
    #pragma unroll
    for (int i = 0; i < (MT * EDIM / 4) / THREADS; i++) {
        int idx = tid + i * THREADS;
        int l = idx >> 4, c4 = idx & 15;
        size_t goff = (size_t)(lbase + l) * 16 + c4;
        float4 xv = x4[goff];
        float4 qv = e4p[(size_t)sidx[l] * 16 + c4];
        out4[goff] = xv;
        out4[LE4 + goff] = qv;
        float4 zh;
        zh.x = (xv.x + qv.x) - xv.x;
        zh.y = (xv.y + qv.y) - xv.y;
        zh.z = (xv.z + qv.z) - xv.z;
        zh.w = (xv.w + qv.w) - xv.w;
        out4[2 * LE4 + goff] = zh;
    }
    if (tid < MT)
        out[3 * (size_t)L_TOTAL * EDIM + lbase + tid] = (float)sidx[tid];
}

extern "C" void kernel_launch(void* const* d_in, const int* in_sizes, int n_in,
                              void* d_out, int out_size) {
    const float* x   = (const float*)d_in[0];
    const float* emb = (const float*)d_in[1];
    float* out       = (float*)d_out;

    vq_prep_kernel<<<64, 128>>>(emb);
    vq_mma_kernel<<<L_TOTAL / MT, THREADS>>>(x, emb, out);
}

// round 16
// speedup vs baseline: 1.4549x; 1.0234x over previous
#include <cuda_runtime.h>
#include <cuda_fp16.h>

#define L_TOTAL 32768
#define KQ      1024
#define EDIM    64
#define MT      32             // latents per CTA (2 warps x 16)
#define CHK     32             // codes per chunk
#define NCHUNK  (KQ / CHK)     // 32 (each warp scans ALL codes)
#define NBUF    3
#define THREADS 64
#define GUARD   8e-2f
#define OFFS    64.0f          // positivity offset folded into MMA accum init

// scratch tables (no cudaMalloc allowed)
__device__ float  g_c[KQ];             // ||e_k||^2 (fp32)
__device__ __half g_ehi[KQ * EDIM];    // fp16-rounded embeddings [k][e]

__device__ __forceinline__ void mma16816(float* d, const unsigned* a,
                                         unsigned b0, unsigned b1) {
    asm volatile(
        "mma.sync.aligned.m16n8k16.row.col.f32.f16.f16.f32 "
        "{%0,%1,%2,%3}, {%4,%5,%6,%7}, {%8,%9}, {%0,%1,%2,%3};"
        : "+f"(d[0]), "+f"(d[1]), "+f"(d[2]), "+f"(d[3])
        : "r"(a[0]), "r"(a[1]), "r"(a[2]), "r"(a[3]), "r"(b0), "r"(b1));
}

__device__ __forceinline__ void ldsm4(unsigned& r0, unsigned& r1,
                                      unsigned& r2, unsigned& r3,
                                      unsigned addr) {
    asm volatile("ldmatrix.sync.aligned.m8n8.x4.shared.b16 {%0,%1,%2,%3}, [%4];"
                 : "=r"(r0), "=r"(r1), "=r"(r2), "=r"(r3) : "r"(addr));
}

__device__ __forceinline__ unsigned packhi(float a, float b) {
    __half2 H = __halves2half2(__float2half_rn(a), __float2half_rn(b));
    return *reinterpret_cast<unsigned*>(&H);
}

__device__ __forceinline__ void cp16(unsigned dst_smem, const void* src) {
    asm volatile("cp.async.cg.shared.global [%0], [%1], 16;"
                 :: "r"(dst_smem), "l"(src) : "memory");
}

// Parallel prep: 8 threads per code row. ||e||^2 via 8-lane shfl tree.
__global__ void vq_prep_kernel(const float* __restrict__ emb) {
    int t   = blockIdx.x * blockDim.x + threadIdx.x;  // 0..8191
    int k   = t >> 3;
    int seg = t & 7;
    const float4* p = reinterpret_cast<const float4*>(emb + k * EDIM + seg * 8);
    float4 v0 = p[0], v1 = p[1];
    float s = v0.x * v0.x + v0.y * v0.y + v0.z * v0.z + v0.w * v0.w
            + v1.x * v1.x + v1.y * v1.y + v1.z * v1.z + v1.w * v1.w;
    uint4 H;
    H.x = packhi(v0.x, v0.y);
    H.y = packhi(v0.z, v0.w);
    H.z = packhi(v1.x, v1.y);
    H.w = packhi(v1.z, v1.w);
    *reinterpret_cast<uint4*>(&g_ehi[k * EDIM + seg * 8]) = H;
    s += __shfl_xor_sync(0xffffffffu, s, 1);
    s += __shfl_xor_sync(0xffffffffu, s, 2);
    s += __shfl_xor_sync(0xffffffffu, s, 4);
    if (seg == 0) g_c[k] = s;
}

// Packed top-3: scores carry their code index in the low 10 mantissa bits.
struct Top3p { float m1, m2, m3; };

__device__ __forceinline__ void ins3p(Top3p& t, float s) {
    float a = fmaxf(t.m1, s);
    t.m1    = fminf(t.m1, s);
    float b = fmaxf(t.m2, a);
    t.m2    = fminf(t.m2, a);
    t.m3    = fminf(t.m3, b);
}

__device__ __forceinline__ float packidx(float s, int col) {
    return __uint_as_float((__float_as_uint(s) & ~1023u) | (unsigned)col);
}

__global__ void __launch_bounds__(THREADS, 7)
vq_mma_kernel(const float* __restrict__ x,
              const float* __restrict__ emb,
              float* __restrict__ out) {
    // Warp-private triple-buffered chunks, XOR-swizzled (4 KB each).
    __shared__ __align__(16) __half sB[2][NBUF][CHK * EDIM];
    __shared__ float cs[KQ];
    __shared__ int   sidx[MT];

    const int tid   = threadIdx.x;
    const int warp  = tid >> 5;        // 0..1: 16-latent tile
    const int lane  = tid & 31;
    const int g     = lane >> 2;       // row within m16 tile
    const int T     = lane & 3;        // thread in quad
    const int lbase = blockIdx.x * MT;

    // stage ||e||^2 (cross-warp: one barrier below covers it)
    #pragma unroll
    for (int i = 0; i < KQ / THREADS; i++)
        cs[tid + i * THREADS] = g_c[tid + i * THREADS];

    const unsigned wbase =
        (unsigned)__cvta_generic_to_shared(&sB[warp][0][0]);

    // Warp-private stage of chunk ch into buf b: 256 cp16 -> 8 per lane.
    // Swizzled layout: byte = row*128 + ((seg ^ (row&7)) << 4).
    auto stage = [&](int ch, int b) {
        const __half* src = g_ehi + (size_t)ch * CHK * EDIM;
        unsigned dbase = wbase + (unsigned)(b * CHK * EDIM * 2);
        #pragma unroll
        for (int i = 0; i < 8; i++) {
            int u   = lane + i * 32;       // 0..255
            int row = u >> 3;
            int seg = u & 7;
            cp16(dbase + (unsigned)(row * 128 + ((seg ^ (row & 7)) << 4)),
                 src + row * EDIM + seg * 8);
        }
        asm volatile("cp.async.commit_group;" ::: "memory");
    };

    // ldmatrix per-lane swizzled offsets (same logical mapping as R15).
    const int r0  = (lane & 7) + ((lane >> 4) << 3);   // 0..15
    const int klo = (lane >> 3) & 1;
    const int rx  = lane & 7;
    const unsigned rowbase = (unsigned)(r0 * 128);
    unsigned xoff[4];
    #pragma unroll
    for (int s = 0; s < 4; s++)
        xoff[s] = (unsigned)((((2 * s + klo) ^ rx) << 4));

    // A fragments: rows r = warp*16+g, r+8 of (-2x), fp16-hi only.
    unsigned ahi[4][4];
    {
        const float* xr0 = x + (size_t)(lbase + warp * 16 + g) * EDIM;
        const float* xr1 = xr0 + 8 * EDIM;
        #pragma unroll
        for (int ks = 0; ks < 4; ks++) {
            int c0 = 16 * ks + 2 * T;
            float2 v;
            v = *reinterpret_cast<const float2*>(xr0 + c0);
            ahi[ks][0] = packhi(-2.f * v.x, -2.f * v.y);
            v = *reinterpret_cast<const float2*>(xr1 + c0);
            ahi[ks][1] = packhi(-2.f * v.x, -2.f * v.y);
            v = *reinterpret_cast<const float2*>(xr0 + c0 + 8);
            ahi[ks][2] = packhi(-2.f * v.x, -2.f * v.y);
            v = *reinterpret_cast<const float2*>(xr1 + c0 + 8);
            ahi[ks][3] = packhi(-2.f * v.x, -2.f * v.y);
        }
    }

    Top3p tp[2];
    tp[0].m1 = tp[0].m2 = tp[0].m3 = 3.4e38f;
    tp[1] = tp[0];

    stage(0, 0);
    stage(1, 1);
    stage(2, 2);
    __syncthreads();   // cs visible to both warps (only pre-loop barrier)

    int bufc = 0;
    #pragma unroll 1
    for (int ch = 0; ch < NCHUNK; ch++) {
        // group for chunk ch complete when <=2 groups outstanding
        asm volatile("cp.async.wait_group 2;" ::: "memory");
        __syncwarp();

        const unsigned base0 = wbase + (unsigned)(bufc * CHK * EDIM * 2)
                             + rowbase;
        const int c0 = ch * CHK;

        #pragma unroll
        for (int nt = 0; nt < 2; nt++) {
            const unsigned base = base0 + (unsigned)(nt * 2048);
            unsigned h0[4], h1[4], h2[4], h3[4];
            ldsm4(h0[0], h0[1], h0[2], h0[3], base + xoff[0]);
            ldsm4(h1[0], h1[1], h1[2], h1[3], base + xoff[1]);
            ldsm4(h2[0], h2[1], h2[2], h2[3], base + xoff[2]);
            ldsm4(h3[0], h3[1], h3[2], h3[3], base + xoff[3]);
            float d[2][4] = {{OFFS,OFFS,OFFS,OFFS},{OFFS,OFFS,OFFS,OFFS}};
            #pragma unroll
            for (int j = 0; j < 2; j++) {
                mma16816(d[j], ahi[0], h0[2*j], h0[2*j+1]);
                mma16816(d[j], ahi[1], h1[2*j], h1[2*j+1]);
                mma16816(d[j], ahi[2], h2[2*j], h2[2*j+1]);
                mma16816(d[j], ahi[3], h3[2*j], h3[2*j+1]);
            }
            #pragma unroll
            for (int j = 0; j < 2; j++) {
                int col = c0 + nt * 16 + 8 * j + 2 * T;
                ins3p(tp[0], packidx(cs[col]     + d[j][0], col));
                ins3p(tp[0], packidx(cs[col + 1] + d[j][1], col + 1));
                ins3p(tp[1], packidx(cs[col]     + d[j][2], col));
                ins3p(tp[1], packidx(cs[col + 1] + d[j][3], col + 1));
            }
        }

        // Refill the buffer just consumed (issued well after its LDSMs).
        if (ch + NBUF < NCHUNK) stage(ch + NBUF, bufc);
        bufc = (bufc == NBUF - 1) ? 0 : bufc + 1;
    }

    // Reduce across the 4 lanes of each quad (xor 1, 2 stay in-quad).
    #pragma unroll
    for (int s = 0; s < 2; s++) {
        #pragma unroll
        for (int m = 1; m < 4; m <<= 1) {
            float o1 = __shfl_xor_sync(0xffffffffu, tp[s].m1, m);
            float o2 = __shfl_xor_sync(0xffffffffu, tp[s].m2, m);
            float o3 = __shfl_xor_sync(0xffffffffu, tp[s].m3, m);
            ins3p(tp[s], o1);
            ins3p(tp[s], o2);
            ins3p(tp[s], o3);
        }
    }

    if (T == 0) {
        #pragma unroll
        for (int s = 0; s < 2; s++) {
            int lr = warp * 16 + g + 8 * s;
            int i1 = (int)(__float_as_uint(tp[s].m1) & 1023u);
            int win = i1;
            // Guard: exact fp32 recheck of all close candidates.
            if (tp[s].m2 - tp[s].m1 < GUARD) {
                int i2 = (int)(__float_as_uint(tp[s].m2) & 1023u);
                const float* xr  = x   + (size_t)(lbase + lr) * EDIM;
                const float* e1r = emb + (size_t)i1 * EDIM;
                const float* e2r = emb + (size_t)i2 * EDIM;
                float d1 = 0.f, d2 = 0.f;
                #pragma unroll 8
                for (int e = 0; e < EDIM; e++) {
                    float xv = xr[e];
                    d1 = fmaf(xv, e1r[e], d1);
                    d2 = fmaf(xv, e2r[e], d2);
                }
                float s1 = fmaf(-2.f, d1, cs[i1]);
                float s2 = fmaf(-2.f, d2, cs[i2]);
                float bs = s1; int bi = i1;
                if (s2 < bs || (s2 == bs && i2 < bi)) { bs = s2; bi = i2; }
                if (tp[s].m3 - tp[s].m1 < GUARD) {
                    int i3 = (int)(__float_as_uint(tp[s].m3) & 1023u);
                    const float* e3r = emb + (size_t)i3 * EDIM;
                    float d3 = 0.f;
                    #pragma unroll 8
                    for (int e = 0; e < EDIM; e++)
                        d3 = fmaf(xr[e], e3r[e], d3);
                    float s3 = fmaf(-2.f, d3, cs[i3]);
                    if (s3 < bs || (s3 == bs && i3 < bi)) { bs = s3; bi = i3; }
                }
                win = bi;
            }
            sidx[lr] = win;
        }
    }
    __syncthreads();

    // Coalesced epilogue: out = [x | quantized | z_hat | indices], fp32.
    const size_t LE4 = (size_t)L_TOTAL * (EDIM / 4);
    const float4* x4  = reinterpret_cast<const float4*>(x);
    const float4* e4p = reinterpret_cast<const float4*>(emb);
    float4* out4 = reinterpret_cast<float4*>(out);
    #pragma unroll
    for (int i = 0; i < (MT * EDIM / 4) / THREADS; i++) {
        int idx = tid + i * THREADS;
        int l = idx >> 4, c4 = idx & 15;
        size_t goff = (size_t)(lbase + l) * 16 + c4;
        float4 xv = x4[goff];
        float4 qv = e4p[(size_t)sidx[l] * 16 + c4];
        out4[goff] = xv;
        out4[LE4 + goff] = qv;
        float4 zh;
        zh.x = (xv.x + qv.x) - xv.x;
        zh.y = (xv.y + qv.y) - xv.y;
        zh.z = (xv.z + qv.z) - xv.z;
        zh.w = (xv.w + qv.w) - xv.w;
        out4[2 * LE4 + goff] = zh;
    }
    if (tid < MT)
        out[3 * (size_t)L_TOTAL * EDIM + lbase + tid] = (float)sidx[tid];
}

extern "C" void kernel_launch(void* const* d_in, const int* in_sizes, int n_in,
                              void* d_out, int out_size) {
    const float* x   = (const float*)d_in[0];
    const float* emb = (const float*)d_in[1];
    float* out       = (float*)d_out;

    vq_prep_kernel<<<64, 128>>>(emb);
    vq_mma_kernel<<<L_TOTAL / MT, THREADS>>>(x, emb, out);
}

// round 17
// speedup vs baseline: 1.5218x; 1.0460x over previous
#include <cuda_runtime.h>
#include <cuda_fp16.h>

#define L_TOTAL 32768
#define KQ      1024
#define EDIM    64
#define MT      16             // latents per CTA (all 4 warps share them)
#define KQTR    256            // codes per k-quarter (one warp each)
#define NBLK    (KQTR / 8)     // 32 n8-blocks per warp
#define THREADS 128
#define GUARD   8e-2f
#define OFFS    64.0f          // positivity offset folded into MMA accum init

// scratch tables (no cudaMalloc allowed)
__device__ float g_c[KQ];                  // ||e_k||^2 (fp32)
__device__ uint4 g_ef[2][KQ / 8][32];      // B fragments: [b0/b1][n8-block][lane]

__device__ __forceinline__ void mma16816(float* d, const unsigned* a,
                                         unsigned b0, unsigned b1) {
    asm volatile(
        "mma.sync.aligned.m16n8k16.row.col.f32.f16.f16.f32 "
        "{%0,%1,%2,%3}, {%4,%5,%6,%7}, {%8,%9}, {%0,%1,%2,%3};"
        : "+f"(d[0]), "+f"(d[1]), "+f"(d[2]), "+f"(d[3])
        : "r"(a[0]), "r"(a[1]), "r"(a[2]), "r"(a[3]), "r"(b0), "r"(b1));
}

__device__ __forceinline__ unsigned packhi(float a, float b) {
    __half2 H = __halves2half2(__float2half_rn(a), __float2half_rn(b));
    return *reinterpret_cast<unsigned*>(&H);
}

// Prep 1: ||e||^2 via 8-lane shfl tree (8 threads per code row).
__global__ void vq_prep_c(const float* __restrict__ emb) {
    int t   = blockIdx.x * blockDim.x + threadIdx.x;  // 0..8191
    int k   = t >> 3;
    int seg = t & 7;
    const float4* p = reinterpret_cast<const float4*>(emb + k * EDIM + seg * 8);
    float4 v0 = p[0], v1 = p[1];
    float s = v0.x * v0.x + v0.y * v0.y + v0.z * v0.z + v0.w * v0.w
            + v1.x * v1.x + v1.y * v1.y + v1.z * v1.z + v1.w * v1.w;
    s += __shfl_xor_sync(0xffffffffu, s, 1);
    s += __shfl_xor_sync(0xffffffffu, s, 2);
    s += __shfl_xor_sync(0xffffffffu, s, 4);
    if (seg == 0) g_c[k] = s;
}

// Prep 2: build the fragment-ordered fp16 table. One thread per (block, lane).
// Lane l of block b supplies B[n = b*8 + (l>>2)][k = ks*16 + 2*(l&3) + 8*h]
// for ks=0..3 (uint4 components), h = plane (b0/b1 of the MMA).
__global__ void vq_prep_frag(const float* __restrict__ emb) {
    int t = blockIdx.x * blockDim.x + threadIdx.x;    // 0..4095
    int b = t >> 5;
    int l = t & 31;
    int n = b * 8 + (l >> 2);
    int kb = 2 * (l & 3);
    const float* row = emb + (size_t)n * EDIM;
    #pragma unroll
    for (int h = 0; h < 2; h++) {
        uint4 v;
        int k0 = kb + 8 * h;
        v.x = packhi(-2.f * row[k0],      -2.f * row[k0 + 1]);
        v.y = packhi(-2.f * row[k0 + 16], -2.f * row[k0 + 17]);
        v.z = packhi(-2.f * row[k0 + 32], -2.f * row[k0 + 33]);
        v.w = packhi(-2.f * row[k0 + 48], -2.f * row[k0 + 49]);
        g_ef[h][b][l] = v;
    }
}

// Packed top-3: scores carry their code index in the low 10 mantissa bits.
// All values positive -> float order == integer order; lower index wins ties.
struct Top3p { float m1, m2, m3; };

__device__ __forceinline__ void ins3p(Top3p& t, float s) {
    float a = fmaxf(t.m1, s);
    t.m1    = fminf(t.m1, s);
    float b = fmaxf(t.m2, a);
    t.m2    = fminf(t.m2, a);
    t.m3    = fminf(t.m3, b);
}

__device__ __forceinline__ float packidx(float s, int col) {
    return __uint_as_float((__float_as_uint(s) & ~1023u) | (unsigned)col);
}

__global__ void __launch_bounds__(THREADS, 6)
vq_mma_kernel(const float* __restrict__ x,
              const float* __restrict__ emb,
              float* __restrict__ out) {
    __shared__ float cs[KQ];
    __shared__ float mbq[3][3][MT];    // quarters 1..3 publish top-3
    __shared__ int   sidx[MT];

    const int tid   = threadIdx.x;
    const int q     = tid >> 5;        // k-quarter (one per warp)
    const int lane  = tid & 31;
    const int g     = lane >> 2;       // row within m16 tile
    const int T     = lane & 3;        // thread in quad
    const int lbase = blockIdx.x * MT;

    // stage ||e||^2 (one-time; single barrier below)
    #pragma unroll
    for (int i = 0; i < KQ / THREADS; i++)
        cs[tid + i * THREADS] = g_c[tid + i * THREADS];

    // A fragments: rows g, g+8 of x (the -2 scale lives in the B table).
    unsigned ahi[4][4];
    {
        const float* xr0 = x + (size_t)(lbase + g) * EDIM;
        const float* xr1 = xr0 + 8 * EDIM;
        #pragma unroll
        for (int ks = 0; ks < 4; ks++) {
            int c0 = 16 * ks + 2 * T;
            float2 v;
            v = *reinterpret_cast<const float2*>(xr0 + c0);
            ahi[ks][0] = packhi(v.x, v.y);
            v = *reinterpret_cast<const float2*>(xr1 + c0);
            ahi[ks][1] = packhi(v.x, v.y);
            v = *reinterpret_cast<const float2*>(xr0 + c0 + 8);
            ahi[ks][2] = packhi(v.x, v.y);
            v = *reinterpret_cast<const float2*>(xr1 + c0 + 8);
            ahi[ks][3] = packhi(v.x, v.y);
        }
    }
    __syncthreads();   // cs visible (only pre-merge barrier)

    Top3p tp[2];
    tp[0].m1 = tp[0].m2 = tp[0].m3 = 3.4e38f;
    tp[1] = tp[0];

    const uint4* pf0 = &g_ef[0][q * NBLK][lane];
    const uint4* pf1 = &g_ef[1][q * NBLK][lane];
    const int qbase  = q * KQTR;

    #pragma unroll 2
    for (int blk = 0; blk < NBLK; blk++) {
        uint4 f0 = __ldg(pf0 + blk * 32);
        uint4 f1 = __ldg(pf1 + blk * 32);
        float d [4] = {OFFS, OFFS, OFFS, OFFS};
        float d2[4] = {0.f, 0.f, 0.f, 0.f};
        mma16816(d,  ahi[0], f0.x, f1.x);
        mma16816(d2, ahi[2], f0.z, f1.z);
        mma16816(d,  ahi[1], f0.y, f1.y);
        mma16816(d2, ahi[3], f0.w, f1.w);
        int col = qbase + blk * 8 + 2 * T;
        float e0 = cs[col], e1 = cs[col + 1];
        ins3p(tp[0], packidx(e0 + (d[0] + d2[0]), col));
        ins3p(tp[0], packidx(e1 + (d[1] + d2[1]), col + 1));
        ins3p(tp[1], packidx(e0 + (d[2] + d2[2]), col));
        ins3p(tp[1], packidx(e1 + (d[3] + d2[3]), col + 1));
    }

    // Reduce across the 4 lanes of each quad (xor 1, 2 stay in-quad).
    #pragma unroll
    for (int s = 0; s < 2; s++) {
        #pragma unroll
        for (int m = 1; m < 4; m <<= 1) {
            float o1 = __shfl_xor_sync(0xffffffffu, tp[s].m1, m);
            float o2 = __shfl_xor_sync(0xffffffffu, tp[s].m2, m);
            float o3 = __shfl_xor_sync(0xffffffffu, tp[s].m3, m);
            ins3p(tp[s], o1);
            ins3p(tp[s], o2);
            ins3p(tp[s], o3);
        }
    }

    // Quarter merge: q=1..3 publish, q=0 inserts (packed index tie-break
    // makes insertion order irrelevant; lower code index wins ties).
    if (q != 0 && T == 0) {
        #pragma unroll
        for (int s = 0; s < 2; s++) {
            int lr = g + 8 * s;
            mbq[q - 1][0][lr] = tp[s].m1;
            mbq[q - 1][1][lr] = tp[s].m2;
            mbq[q - 1][2][lr] = tp[s].m3;
        }
    }
    __syncthreads();

    if (q == 0 && T == 0) {
        #pragma unroll
        for (int s = 0; s < 2; s++) {
            int lr = g + 8 * s;
            #pragma unroll
            for (int qq = 0; qq < 3; qq++) {
                ins3p(tp[s], mbq[qq][0][lr]);
                ins3p(tp[s], mbq[qq][1][lr]);
                ins3p(tp[s], mbq[qq][2][lr]);
            }

            int i1 = (int)(__float_as_uint(tp[s].m1) & 1023u);
            int win = i1;
            // Guard: exact fp32 recheck of all close candidates.
            if (tp[s].m2 - tp[s].m1 < GUARD) {
                int i2 = (int)(__float_as_uint(tp[s].m2) & 1023u);
                const float* xr  = x   + (size_t)(lbase + lr) * EDIM;
                const float* e1r = emb + (size_t)i1 * EDIM;
                const float* e2r = emb + (size_t)i2 * EDIM;
                float d1 = 0.f, d2v = 0.f;
                #pragma unroll 8
                for (int e = 0; e < EDIM; e++) {
                    float xv = xr[e];
                    d1  = fmaf(xv, e1r[e], d1);
                    d2v = fmaf(xv, e2r[e], d2v);
                }
                float s1 = fmaf(-2.f, d1,  cs[i1]);
                float s2 = fmaf(-2.f, d2v, cs[i2]);
                float bs = s1; int bi = i1;
                if (s2 < bs || (s2 == bs && i2 < bi)) { bs = s2; bi = i2; }
                if (tp[s].m3 - tp[s].m1 < GUARD) {
                    int i3 = (int)(__float_as_uint(tp[s].m3) & 1023u);
                    const float* e3r = emb + (size_t)i3 * EDIM;
                    float d3 = 0.f;
                    #pragma unroll 8
                    for (int e = 0; e < EDIM; e++)
                        d3 = fmaf(xr[e], e3r[e], d3);
                    float s3 = fmaf(-2.f, d3, cs[i3]);
                    if (s3 < bs || (s3 == bs && i3 < bi)) { bs = s3; bi = i3; }
                }
                win = bi;
            }
            sidx[lr] = win;
        }
    }
    __syncthreads();

    // Coalesced epilogue: out = [x | quantized | z_hat | indices], fp32.
    const size_t LE4 = (size_t)L_TOTAL * (EDIM / 4);
    const float4* x4  = reinterpret_cast<const float4*>(x);
    const float4* e4p = reinterpret_cast<const float4*>(emb);
    float4* out4 = reinterpret_cast<float4*>(out);
    #pragma unroll
    for (int i = 0; i < (MT * EDIM / 4) / THREADS; i++) {
        int idx = tid + i * THREADS;
        int l = idx >> 4, c4 = idx & 15;
        size_t goff = (size_t)(lbase + l) * 16 + c4;
        float4 xv = x4[goff];
        float4 qv = e4p[(size_t)sidx[l] * 16 + c4];
        out4[goff] = xv;
        out4[LE4 + goff] = qv;
        float4 zh;
        zh.x = (xv.x + qv.x) - xv.x;
        zh.y = (xv.y + qv.y) - xv.y;
        zh.z = (xv.z + qv.z) - xv.z;
        zh.w = (xv.w + qv.w) - xv.w;
        out4[2 * LE4 + goff] = zh;
    }
    if (tid < MT)
        out[3 * (size_t)L_TOTAL * EDIM + lbase + tid] = (float)sidx[tid];
}

extern "C" void kernel_launch(void* const* d_in, const int* in_sizes, int n_in,
                              void* d_out, int out_size) {
    const float* x   = (const float*)d_in[0];
    const float* emb = (const float*)d_in[1];
    float* out       = (float*)d_out;

    vq_prep_c<<<64, 128>>>(emb);
    vq_prep_frag<<<32, 128>>>(emb);
    vq_mma_kernel<<<L_TOTAL / MT, THREADS>>>(x, emb, out);
}